// round 1
// baseline (speedup 1.0000x reference)
#include <cuda_runtime.h>

#define ALPHA 0.1f
#define BETA  0.96f
#define VTHR  2.0f

// One thread owns 4 adjacent channels (a float4 lane) and scans all T steps,
// carrying (syn, mem) state in registers. x loads are independent of the
// recurrence, so we prefetch x[t+1] while computing step t.
__global__ __launch_bounds__(256, 1)
void snn_scan_kernel(const float4* __restrict__ x,
                     float4* __restrict__ spk_out,
                     float4* __restrict__ syn_out,
                     float4* __restrict__ mem_out,
                     int T, int BN4)
{
    int idx = blockIdx.x * blockDim.x + threadIdx.x;
    if (idx >= BN4) return;

    float syn0 = 0.f, syn1 = 0.f, syn2 = 0.f, syn3 = 0.f;
    float mem0 = 0.f, mem1 = 0.f, mem2 = 0.f, mem3 = 0.f;

    // prefetch t=0
    float4 xv = x[idx];

    for (int t = 0; t < T; ++t) {
        size_t row = (size_t)t * (size_t)BN4 + (size_t)idx;

        // prefetch next timestep's input (independent of the recurrence)
        float4 xn;
        if (t + 1 < T) xn = x[row + (size_t)BN4];

        float4 s, so, mo;

        // ---- component 0 ----
        {
            bool reset = (mem0 > VTHR);
            syn0 = fmaf(ALPHA, syn0, xv.x);
            mem0 = fmaf(BETA,  mem0, syn0);
            if (reset) { syn0 = 0.f; mem0 = 0.f; }
            s.x  = (mem0 > VTHR) ? 1.f : 0.f;
            so.x = syn0; mo.x = mem0;
        }
        // ---- component 1 ----
        {
            bool reset = (mem1 > VTHR);
            syn1 = fmaf(ALPHA, syn1, xv.y);
            mem1 = fmaf(BETA,  mem1, syn1);
            if (reset) { syn1 = 0.f; mem1 = 0.f; }
            s.y  = (mem1 > VTHR) ? 1.f : 0.f;
            so.y = syn1; mo.y = mem1;
        }
        // ---- component 2 ----
        {
            bool reset = (mem2 > VTHR);
            syn2 = fmaf(ALPHA, syn2, xv.z);
            mem2 = fmaf(BETA,  mem2, syn2);
            if (reset) { syn2 = 0.f; mem2 = 0.f; }
            s.z  = (mem2 > VTHR) ? 1.f : 0.f;
            so.z = syn2; mo.z = mem2;
        }
        // ---- component 3 ----
        {
            bool reset = (mem3 > VTHR);
            syn3 = fmaf(ALPHA, syn3, xv.w);
            mem3 = fmaf(BETA,  mem3, syn3);
            if (reset) { syn3 = 0.f; mem3 = 0.f; }
            s.w  = (mem3 > VTHR) ? 1.f : 0.f;
            so.w = syn3; mo.w = mem3;
        }

        spk_out[row] = s;
        syn_out[row] = so;
        mem_out[row] = mo;

        xv = xn;
    }
}

extern "C" void kernel_launch(void* const* d_in, const int* in_sizes, int n_in,
                              void* d_out, int out_size)
{
    const float* x = (const float*)d_in[0];
    float* out = (float*)d_out;

    const int T = 512;
    int total = in_sizes[0];          // T * B * N
    int BN = total / T;               // 32 * 4096 = 131072
    int BN4 = BN / 4;                 // 32768 float4 lanes

    float4* spk = (float4*)out;
    float4* syn = (float4*)(out + (size_t)total);
    float4* mem = (float4*)(out + 2 * (size_t)total);

    int threads = 256;
    int blocks = (BN4 + threads - 1) / threads;   // 128
    snn_scan_kernel<<<blocks, threads>>>((const float4*)x, spk, syn, mem, T, BN4);
}

// round 2
// speedup vs baseline: 1.7701x; 1.7701x over previous
#include <cuda_runtime.h>

#define ALPHA 0.1f
#define BETA  0.96f
#define VTHR  2.0f

__device__ __forceinline__ void snn_step(float xv, float& syn, float& mem,
                                         float& spk_o, float& syn_o, float& mem_o)
{
    bool reset = (mem > VTHR);
    syn = fmaf(ALPHA, syn, xv);
    mem = fmaf(BETA,  mem, syn);
    if (reset) { syn = 0.f; mem = 0.f; }
    spk_o = (mem > VTHR) ? 1.f : 0.f;
    syn_o = syn;
    mem_o = mem;
}

__device__ __forceinline__ void snn_step4(float4 xv,
                                          float& s0, float& s1, float& s2, float& s3,
                                          float& m0, float& m1, float& m2, float& m3,
                                          float4* __restrict__ spk,
                                          float4* __restrict__ syn,
                                          float4* __restrict__ mem,
                                          size_t row)
{
    float4 sp, so, mo;
    snn_step(xv.x, s0, m0, sp.x, so.x, mo.x);
    snn_step(xv.y, s1, m1, sp.y, so.y, mo.y);
    snn_step(xv.z, s2, m2, sp.z, so.z, mo.z);
    snn_step(xv.w, s3, m3, sp.w, so.w, mo.w);
    __stcs(spk + row, sp);
    __stcs(syn + row, so);
    __stcs(mem + row, mo);
}

// One thread owns 4 adjacent channels; scans all T steps with (syn, mem) in
// registers. Time loop unrolled by 4 with a 4-deep independent prefetch batch
// so 4 LDG.128 are always in flight per thread.
__global__ __launch_bounds__(128, 8)
void snn_scan_kernel(const float4* __restrict__ x,
                     float4* __restrict__ spk_out,
                     float4* __restrict__ syn_out,
                     float4* __restrict__ mem_out,
                     int T, int BN4)
{
    int idx = blockIdx.x * blockDim.x + threadIdx.x;
    if (idx >= BN4) return;

    float s0 = 0.f, s1 = 0.f, s2 = 0.f, s3 = 0.f;
    float m0 = 0.f, m1 = 0.f, m2 = 0.f, m3 = 0.f;

    const size_t stride = (size_t)BN4;
    const float4* xp = x + idx;

    // prefetch batch t = 0..3
    float4 xa = __ldcs(xp);
    float4 xb = __ldcs(xp + stride);
    float4 xc = __ldcs(xp + 2 * stride);
    float4 xd = __ldcs(xp + 3 * stride);

    for (int t = 0; t < T; t += 4) {
        // issue next batch's loads first (independent of the recurrence);
        // clamp so the last iteration re-reads valid rows (values unused)
        int tn = (t + 4 < T) ? (t + 4) : t;
        const float4* xq = x + (size_t)tn * stride + idx;
        float4 na = __ldcs(xq);
        float4 nb = __ldcs(xq + stride);
        float4 nc = __ldcs(xq + 2 * stride);
        float4 nd = __ldcs(xq + 3 * stride);

        size_t row = (size_t)t * stride + idx;
        snn_step4(xa, s0, s1, s2, s3, m0, m1, m2, m3, spk_out, syn_out, mem_out, row);
        row += stride;
        snn_step4(xb, s0, s1, s2, s3, m0, m1, m2, m3, spk_out, syn_out, mem_out, row);
        row += stride;
        snn_step4(xc, s0, s1, s2, s3, m0, m1, m2, m3, spk_out, syn_out, mem_out, row);
        row += stride;
        snn_step4(xd, s0, s1, s2, s3, m0, m1, m2, m3, spk_out, syn_out, mem_out, row);

        xa = na; xb = nb; xc = nc; xd = nd;
    }
}

extern "C" void kernel_launch(void* const* d_in, const int* in_sizes, int n_in,
                              void* d_out, int out_size)
{
    const float* x = (const float*)d_in[0];
    float* out = (float*)d_out;

    const int T = 512;
    int total = in_sizes[0];          // T * B * N
    int BN = total / T;               // 131072
    int BN4 = BN / 4;                 // 32768 float4 lanes

    float4* spk = (float4*)out;
    float4* syn = (float4*)(out + (size_t)total);
    float4* mem = (float4*)(out + 2 * (size_t)total);

    int threads = 128;
    int blocks = (BN4 + threads - 1) / threads;   // 256 blocks -> covers all 148 SMs
    snn_scan_kernel<<<blocks, threads>>>((const float4*)x, spk, syn, mem, T, BN4);
}

// round 4
// speedup vs baseline: 1.9214x; 1.0855x over previous
#include <cuda_runtime.h>

#define ALPHA 0.1f
#define BETA  0.96f
#define VTHR  2.0f
#define DEPTH 8

__device__ __forceinline__ void snn_step(float xv, float& syn, float& mem,
                                         float& spk_o, float& syn_o, float& mem_o)
{
    bool reset = (mem > VTHR);
    syn = fmaf(ALPHA, syn, xv);
    mem = fmaf(BETA,  mem, syn);
    if (reset) { syn = 0.f; mem = 0.f; }
    spk_o = (mem > VTHR) ? 1.f : 0.f;
    syn_o = syn;
    mem_o = mem;
}

__device__ __forceinline__ void snn_step4(float4 xv,
                                          float& s0, float& s1, float& s2, float& s3,
                                          float& m0, float& m1, float& m2, float& m3,
                                          float4* __restrict__ spk,
                                          float4* __restrict__ syn,
                                          float4* __restrict__ mem,
                                          size_t row)
{
    float4 sp, so, mo;
    snn_step(xv.x, s0, m0, sp.x, so.x, mo.x);
    snn_step(xv.y, s1, m1, sp.y, so.y, mo.y);
    snn_step(xv.z, s2, m2, sp.z, so.z, mo.z);
    snn_step(xv.w, s3, m3, sp.w, so.w, mo.w);
    __stcs(spk + row, sp);
    __stcs(syn + row, so);
    __stcs(mem + row, mo);
}

// One thread owns 4 adjacent channels; scans all T steps with (syn, mem) in
// registers. Time loop unrolled by DEPTH=8 with an 8-deep independent
// prefetch batch (8 LDG.128 in flight per thread). 1-warp blocks give a
// fine-grained, near-balanced distribution across all 148 SMs.
__global__ __launch_bounds__(32, 16)
void snn_scan_kernel(const float4* __restrict__ x,
                     float4* __restrict__ spk_out,
                     float4* __restrict__ syn_out,
                     float4* __restrict__ mem_out,
                     int T, int BN4)
{
    int idx = blockIdx.x * blockDim.x + threadIdx.x;
    if (idx >= BN4) return;

    float s0 = 0.f, s1 = 0.f, s2 = 0.f, s3 = 0.f;
    float m0 = 0.f, m1 = 0.f, m2 = 0.f, m3 = 0.f;

    const size_t stride = (size_t)BN4;
    const size_t batch_stride = (size_t)DEPTH * stride;

    // prefetch batch t = 0..DEPTH-1
    float4 pf[DEPTH];
    const float4* xp = x + idx;
    #pragma unroll
    for (int i = 0; i < DEPTH; ++i)
        pf[i] = __ldcs(xp + (size_t)i * stride);

    for (int t = 0; t < T; t += DEPTH) {
        // issue next batch's loads first (independent of the recurrence);
        // clamp so the final iteration re-reads valid rows (values unused)
        const float4* xq = (t + DEPTH < T) ? (xp + batch_stride) : xp;
        float4 nx[DEPTH];
        #pragma unroll
        for (int i = 0; i < DEPTH; ++i)
            nx[i] = __ldcs(xq + (size_t)i * stride);

        size_t row = (size_t)t * stride + idx;
        #pragma unroll
        for (int i = 0; i < DEPTH; ++i) {
            snn_step4(pf[i], s0, s1, s2, s3, m0, m1, m2, m3,
                      spk_out, syn_out, mem_out, row);
            row += stride;
        }

        #pragma unroll
        for (int i = 0; i < DEPTH; ++i)
            pf[i] = nx[i];

        xp += batch_stride;
    }
}

extern "C" void kernel_launch(void* const* d_in, const int* in_sizes, int n_in,
                              void* d_out, int out_size)
{
    const float* x = (const float*)d_in[0];
    float* out = (float*)d_out;

    const int T = 512;
    int total = in_sizes[0];          // T * B * N
    int BN = total / T;               // 131072
    int BN4 = BN / 4;                 // 32768 float4 lanes

    float4* spk = (float4*)out;
    float4* syn = (float4*)(out + (size_t)total);
    float4* mem = (float4*)(out + 2 * (size_t)total);

    int threads = 32;
    int blocks = (BN4 + threads - 1) / threads;   // 1024 one-warp blocks
    snn_scan_kernel<<<blocks, threads>>>((const float4*)x, spk, syn, mem, T, BN4);
}